// round 15
// baseline (speedup 1.0000x reference)
#include <cuda_runtime.h>
#include <math.h>
#include <stdint.h>

#define NN 50000      // nodes
#define NE 800000     // edges
#define NG 128        // graphs
#define FX 92         // node feature dim
#define FE 41         // edge feature dim
#define HD 64         // hidden
#define NCV 3         // conv layers
#define BN_EPS 1e-5f
#define NBLK 196      // scan blocks
#define EPW 16        // rows/edges per warp-strip

typedef unsigned long long ull;
typedef long long ll;

// ---------------- device scratch ----------------
__device__ float g_h[NN * HD];
__device__ float g_acc[NN * HD];
__device__ float g_HN[NN * 4 * HD];                   // [N,256]: [f_i|s_i|f_j|s_j]
__device__ float g_Wce[NCV * FE * 2 * HD];
__device__ float g_bce[NCV * 2 * HD];
__device__ float g_Wnode[NCV * HD * 4 * HD];
__device__ uint2 g_Bpe[NCV * 3072];                   // prepacked edge B fragments (tf32)
__device__ float g_sum[NCV * HD];
__device__ float g_sumsq[NCV * HD];
__device__ float g_gsum[NG * HD];
__device__ float g_gcnt[NG];
// sort-by-dst machinery
__device__ int   g_deg[NN];
__device__ int   g_cursor[NN];
__device__ int   g_rp[NN];
__device__ int   g_bsum[256];
__device__ int   g_srcp[NE];
__device__ int   g_dstp[NE];
__device__ float g_eap[(ll)NE * FE];   // permuted edge_attr (row-major, sorted order)

// ---------------- helpers ----------------
__device__ __forceinline__ float sigmoid_f(float x) {
    float t;
    asm("tanh.approx.f32 %0, %1;" : "=f"(t) : "f"(x * 0.5f));
    return fmaf(t, 0.5f, 0.5f);
}
// softplus: log1p(e^-|x|) via deg-6 poly in t = 2e^-|x|-1 (abs err ~1.5e-6)
__device__ __forceinline__ float softplus_f(float x) {
    float u = __expf(-fabsf(x));
    float t = fmaf(2.0f, u, -1.0f);
    float p = -0.00027213f;
    p = fmaf(p, t, 0.00095152f);
    p = fmaf(p, t, -0.0030580f);
    p = fmaf(p, t, 0.0122790f);
    p = fmaf(p, t, -0.0555608f);
    p = fmaf(p, t, 0.3333420f);
    p = fmaf(p, t, 0.4054640f);
    return fmaxf(x, 0.0f) + p;
}
__device__ __forceinline__ void red4(float* p, float4 v) {
    asm volatile("red.global.add.v4.f32 [%0], {%1,%2,%3,%4};"
                 :: "l"(p), "f"(v.x), "f"(v.y), "f"(v.z), "f"(v.w) : "memory");
}
__device__ __forceinline__ void red2(float* p, float a, float b) {
    asm volatile("red.global.add.v2.f32 [%0], {%1,%2};"
                 :: "l"(p), "f"(a), "f"(b) : "memory");
}
__device__ __forceinline__ uint32_t to_tf32(float f) {
    uint32_t r; asm("cvt.rna.tf32.f32 %0, %1;" : "=r"(r) : "f"(f)); return r;
}
__device__ __forceinline__ void mma_tf32(float c[4], uint32_t a0, uint32_t a1,
                                         uint32_t a2, uint32_t a3,
                                         uint32_t b0, uint32_t b1) {
    asm volatile(
        "mma.sync.aligned.m16n8k8.row.col.f32.tf32.tf32.f32 "
        "{%0,%1,%2,%3}, {%4,%5,%6,%7}, {%8,%9}, {%0,%1,%2,%3};"
        : "+f"(c[0]), "+f"(c[1]), "+f"(c[2]), "+f"(c[3])
        : "r"(a0), "r"(a1), "r"(a2), "r"(a3), "r"(b0), "r"(b1));
}

// ---------------- prep: fold weights + zero counters/stats ----------------
__global__ void prep_kernel(const float* __restrict__ W_emb2, const float* __restrict__ b_emb2,
                            const float* __restrict__ Wf, const float* __restrict__ bf,
                            const float* __restrict__ Ws, const float* __restrict__ bs) {
    int idx = blockIdx.x * blockDim.x + threadIdx.x;
    const int N_WCE = NCV * FE * 2 * HD;
    const int N_BCE = NCV * 2 * HD;
    const int N_WND = NCV * HD * 4 * HD;
    if (idx < NN) { g_deg[idx] = 0; g_cursor[idx] = 0; }
    if (idx < NCV * HD) { g_sum[idx] = 0.f; g_sumsq[idx] = 0.f; }
    if (idx < NG * HD) g_gsum[idx] = 0.f;
    if (idx < NG) g_gcnt[idx] = 0.f;
    if (idx < N_WCE) {
        int j = idx % (2 * HD);
        int k = (idx / (2 * HD)) % FE;
        int a = idx / (2 * HD * FE);
        const float* Wb = (j < HD) ? Wf : Ws;
        int jj = j & (HD - 1);
        float s = 0.f;
        #pragma unroll 8
        for (int m = 0; m < HD; m++)
            s = fmaf(W_emb2[k * HD + m], Wb[(a * 3 * HD + 2 * HD + m) * HD + jj], s);
        g_Wce[idx] = s;
    } else if (idx < N_WCE + N_BCE) {
        int t = idx - N_WCE;
        int j = t % (2 * HD);
        int a = t / (2 * HD);
        const float* Wb = (j < HD) ? Wf : Ws;
        const float* bb = (j < HD) ? bf : bs;
        int jj = j & (HD - 1);
        float s = bb[a * HD + jj];
        #pragma unroll 8
        for (int m = 0; m < HD; m++)
            s = fmaf(b_emb2[m], Wb[(a * 3 * HD + 2 * HD + m) * HD + jj], s);
        g_bce[t] = s;
    } else if (idx < N_WCE + N_BCE + N_WND) {
        int t = idx - N_WCE - N_BCE;
        int j = t % (4 * HD);
        int m = (t / (4 * HD)) % HD;
        int a = t / (4 * HD * HD);
        int blk = j / HD;                 // 0:f_i 1:s_i 2:f_j 3:s_j
        int jj = j & (HD - 1);
        const float* Wsel = (blk & 1) ? Ws : Wf;
        int roff = (blk >= 2) ? HD : 0;
        g_Wnode[t] = Wsel[(a * 3 * HD + roff + m) * HD + jj];
    }
}

// prepack edge B fragments into global (reads g_Wce, so separate launch)
__global__ void bp_pack_kernel() {
    int i = blockIdx.x * blockDim.x + threadIdx.x;
    if (i >= NCV * 3072) return;
    int a = i / 3072, j = i - a * 3072;
    int l = j & 31, nt = (j >> 5) & 15, kk = j >> 9;
    int g = l >> 2, t = l & 3;
    int k0 = 8 * kk + t, k1 = k0 + 4, n = 8 * nt + g;
    const float* Wce = g_Wce + a * FE * 128;
    uint32_t b0 = (k0 < FE) ? to_tf32(Wce[k0 * 128 + n]) : 0u;
    uint32_t b1 = (k1 < FE) ? to_tf32(Wce[k1 * 128 + n]) : 0u;
    g_Bpe[i] = make_uint2(b0, b1);
}

// ---------------- sort by dst ----------------
__global__ void hist_kernel(const int* __restrict__ ei) {
    int e = blockIdx.x * blockDim.x + threadIdx.x;
    if (e < NE) atomicAdd(&g_deg[ei[NE + e]], 1);
}
__global__ void scan1_kernel() {
    __shared__ int s[256];
    int tid = threadIdx.x;
    int i = blockIdx.x * 256 + tid;
    int v = (i < NN) ? g_deg[i] : 0;
    s[tid] = v; __syncthreads();
    #pragma unroll
    for (int off = 1; off < 256; off <<= 1) {
        int t = (tid >= off) ? s[tid - off] : 0;
        __syncthreads();
        s[tid] += t;
        __syncthreads();
    }
    if (i < NN) g_rp[i] = s[tid] - v;
    if (tid == 255) g_bsum[blockIdx.x] = s[255];
}
__global__ void scan2_kernel() {
    __shared__ int s[256];
    int tid = threadIdx.x;
    int v = (tid < NBLK) ? g_bsum[tid] : 0;
    s[tid] = v; __syncthreads();
    #pragma unroll
    for (int off = 1; off < 256; off <<= 1) {
        int t = (tid >= off) ? s[tid - off] : 0;
        __syncthreads();
        s[tid] += t;
        __syncthreads();
    }
    if (tid < NBLK) g_bsum[tid] = s[tid] - v;
}
__global__ void scan3_kernel() {
    int i = blockIdx.x * 256 + threadIdx.x;
    if (i < NN) g_rp[i] += g_bsum[blockIdx.x];
}
__global__ void scatter_perm_kernel(const int* __restrict__ ei, const float* __restrict__ ea) {
    int w = (blockIdx.x * blockDim.x + threadIdx.x) >> 5;
    int lane = threadIdx.x & 31;
    int nw = (gridDim.x * blockDim.x) >> 5;
    for (int e = w; e < NE; e += nw) {
        int pos = 0;
        if (lane == 0) {
            int d = ei[NE + e];
            int s = ei[e];
            pos = g_rp[d] + atomicAdd(&g_cursor[d], 1);
            g_srcp[pos] = s;
            g_dstp[pos] = d;
        }
        pos = __shfl_sync(0xffffffffu, pos, 0);
        for (int k = lane; k < FE; k += 32)
            g_eap[(ll)pos * FE + k] = ea[(ll)e * FE + k];
    }
}

// ---------------- embedding GEMM: mma.sync tf32, warp-autonomous ----------------
#define EM_ATLD 24
#define EM_SMBP 512
#define EM_SMWR (EM_SMBP + 3072 * 8)          // 25088
#define EM_WREG 9216
#define EM_SMEM (EM_SMWR + 16 * EM_WREG)       // 172544

__global__ __launch_bounds__(512, 1) void emb_mma_kernel(
        const float* __restrict__ x, const float* __restrict__ W, const float* __restrict__ b) {
    extern __shared__ char base[];
    float* bias_s = (float*)base;
    uint2* Bp = (uint2*)(base + EM_SMBP);
    int tid = threadIdx.x;
    int lane = tid & 31, wid = tid >> 5;
    int gid = lane >> 2, tig = lane & 3;
    uint32_t* Atw = (uint32_t*)(base + EM_SMWR + wid * EM_WREG);

    if (tid < HD) bias_s[tid] = b[tid];
    for (int i = tid; i < 3072; i += 512) {
        int l = i & 31, nt = (i >> 5) & 7, kk = i >> 8;
        int g = l >> 2, t = l & 3;
        int k0 = 8 * kk + t, k1 = k0 + 4;
        uint32_t b0 = (k0 < FX) ? to_tf32(W[k0 * HD + 8 * nt + g]) : 0u;
        uint32_t b1 = (k1 < FX) ? to_tf32(W[k1 * HD + 8 * nt + g]) : 0u;
        Bp[i] = make_uint2(b0, b1);
    }
    for (int i = lane; i < 4 * EM_ATLD; i += 32) Atw[FX * EM_ATLD + i] = 0u;
    __syncthreads();

    const int nstrips = NN / EPW;
    int gw = blockIdx.x * 16 + wid;
    int nw = gridDim.x * 16;
    for (int s = gw; s < nstrips; s += nw) {
        int row0 = s * EPW;
        __syncwarp();
        const float4* s4 = reinterpret_cast<const float4*>(&x[(ll)row0 * FX]);
        #pragma unroll
        for (int j = 0; j < 12; j++) {
            int i4 = lane + 32 * j;
            if (i4 < 368) {
                float4 v = s4[i4];
                int r = __float2int_rd((i4 + 0.5f) * (1.0f / 23.0f));
                int k0 = (i4 - 23 * r) * 4;
                Atw[(k0 + 0) * EM_ATLD + r] = to_tf32(v.x);
                Atw[(k0 + 1) * EM_ATLD + r] = to_tf32(v.y);
                Atw[(k0 + 2) * EM_ATLD + r] = to_tf32(v.z);
                Atw[(k0 + 3) * EM_ATLD + r] = to_tf32(v.w);
            }
        }
        __syncwarp();
        float c[8][4];
        #pragma unroll
        for (int nt = 0; nt < 8; nt++)
            #pragma unroll
            for (int q = 0; q < 4; q++) c[nt][q] = 0.f;
        #pragma unroll
        for (int kk = 0; kk < 12; kk++) {
            uint32_t a0 = Atw[(8 * kk + tig) * EM_ATLD + gid];
            uint32_t a1 = Atw[(8 * kk + tig) * EM_ATLD + gid + 8];
            uint32_t a2 = Atw[(8 * kk + tig + 4) * EM_ATLD + gid];
            uint32_t a3 = Atw[(8 * kk + tig + 4) * EM_ATLD + gid + 8];
            #pragma unroll
            for (int nt = 0; nt < 8; nt++) {
                uint2 bb = Bp[(kk * 8 + nt) * 32 + lane];
                mma_tf32(c[nt], a0, a1, a2, a3, bb.x, bb.y);
            }
        }
        #pragma unroll
        for (int nt = 0; nt < 8; nt++) {
            int col = nt * 8 + 2 * tig;
            float2 bi = *reinterpret_cast<const float2*>(&bias_s[col]);
            float2 v0 = make_float2(c[nt][0] + bi.x, c[nt][1] + bi.y);
            float2 v1 = make_float2(c[nt][2] + bi.x, c[nt][3] + bi.y);
            *reinterpret_cast<float2*>(&g_h[(ll)(row0 + gid) * HD + col]) = v0;
            *reinterpret_cast<float2*>(&g_acc[(ll)(row0 + gid) * HD + col]) = v0;
            *reinterpret_cast<float2*>(&g_h[(ll)(row0 + gid + 8) * HD + col]) = v1;
            *reinterpret_cast<float2*>(&g_acc[(ll)(row0 + gid + 8) * HD + col]) = v1;
        }
    }
}

// ---------------- node GEMM: mma.sync tf32, warp-autonomous, fused BN ----------------
#define ND_ATLD 24
#define ND_SMBP 512
#define ND_SMWR 66048
#define ND_WREG 6144
#define ND_SMEM (ND_SMWR + 16 * ND_WREG)   // 164352

__global__ __launch_bounds__(512, 1) void node_mma_kernel(
        const float* __restrict__ src, const float* __restrict__ Wn,
        float* __restrict__ HN, float* __restrict__ wb,
        const float* __restrict__ bnsum, const float* __restrict__ bnsq,
        const float* __restrict__ bngam, const float* __restrict__ bnbet) {
    extern __shared__ char base[];
    float* scl = (float*)base;
    float* sft = scl + HD;
    uint2* Bp = (uint2*)(base + ND_SMBP);
    int tid = threadIdx.x;
    int lane = tid & 31, wid = tid >> 5;
    int gid = lane >> 2, tig = lane & 3;
    uint32_t* Atw = (uint32_t*)(base + ND_SMWR + wid * ND_WREG);
    int dobn = (bnsum != nullptr);

    if (dobn && tid < HD) {
        const float invn = 1.0f / (float)NN;
        float mu = bnsum[tid] * invn;
        float var = fmaxf(bnsq[tid] * invn - mu * mu, 0.f);
        float sc = rsqrtf(var + BN_EPS) * bngam[tid];
        scl[tid] = sc;
        sft[tid] = bnbet[tid] - mu * sc;
    }
    for (int i = tid; i < 8192; i += 512) {
        int l = i & 31, nt = (i >> 5) & 31, kk = i >> 10;
        int g = l >> 2, t = l & 3;
        Bp[i] = make_uint2(to_tf32(Wn[(8 * kk + t) * 256 + 8 * nt + g]),
                           to_tf32(Wn[(8 * kk + t + 4) * 256 + 8 * nt + g]));
    }
    __syncthreads();

    const int nstrips = NN / EPW;
    int gw = blockIdx.x * 16 + wid;
    int nw = gridDim.x * 16;
    for (int s = gw; s < nstrips; s += nw) {
        int row0 = s * EPW;
        __syncwarp();
        for (int i = lane; i < EPW * HD; i += 32) {
            int r = i >> 6, k = i & 63;
            int gr = row0 + r;
            float v = src[(ll)gr * HD + k];
            if (dobn) {
                v = fmaxf(fmaf(v, scl[k], sft[k]), 0.f);
                wb[(ll)gr * HD + k] = v;
            }
            Atw[k * ND_ATLD + r] = to_tf32(v);
        }
        __syncwarp();
        #pragma unroll
        for (int h = 0; h < 2; h++) {
            float c[16][4];
            #pragma unroll
            for (int nt = 0; nt < 16; nt++)
                #pragma unroll
                for (int q = 0; q < 4; q++) c[nt][q] = 0.f;
            #pragma unroll
            for (int kk = 0; kk < 8; kk++) {
                uint32_t a0 = Atw[(8 * kk + tig) * ND_ATLD + gid];
                uint32_t a1 = Atw[(8 * kk + tig) * ND_ATLD + gid + 8];
                uint32_t a2 = Atw[(8 * kk + tig + 4) * ND_ATLD + gid];
                uint32_t a3 = Atw[(8 * kk + tig + 4) * ND_ATLD + gid + 8];
                #pragma unroll
                for (int nt = 0; nt < 16; nt++) {
                    uint2 b = Bp[(kk * 32 + h * 16 + nt) * 32 + lane];
                    mma_tf32(c[nt], a0, a1, a2, a3, b.x, b.y);
                }
            }
            #pragma unroll
            for (int nt = 0; nt < 16; nt++) {
                int col = h * 128 + nt * 8 + 2 * tig;
                *reinterpret_cast<float2*>(&HN[(ll)(row0 + gid) * 256 + col]) =
                    make_float2(c[nt][0], c[nt][1]);
                *reinterpret_cast<float2*>(&HN[(ll)(row0 + gid + 8) * 256 + col]) =
                    make_float2(c[nt][2], c[nt][3]);
            }
        }
    }
}

// ---------------- fused edge kernel: 3 CTA/SM, halved register tiles ----------------
// per-warp region (WREG2 = 8832B):
//   [0,4224)     EWf (16 x 66 floats)           written in f-half
//   [4224,8832)  At (48 x 24 tf32, 4608B)       live staging..mma
//                EWs (16 x 66 floats, 4224B)    overwrites At rows 0..43 in s-half
#define ATW_LD 24
#define EW_LDH 66
#define RG2_OFF 4224
#define WREG2  8832
#define FE_SMEM (512 + 8 * WREG2)   // 71168

__global__ __launch_bounds__(256, 3) void fused_edge_kernel(
        float* __restrict__ acc,
        const uint2* __restrict__ Bpe, const float* __restrict__ bce) {
    extern __shared__ char base[];
    float* bias_s = (float*)(base);
    int tid = threadIdx.x;
    int lane = tid & 31, wid = tid >> 5;
    int gid = lane >> 2, tig = lane & 3;
    char* wreg = base + 512 + wid * WREG2;
    float*    EWf = (float*)wreg;
    uint32_t* Atw = (uint32_t*)(wreg + RG2_OFF);
    float*    EWs = (float*)(wreg + RG2_OFF);

    if (tid < 128) bias_s[tid] = bce[tid];
    // zero At padding rows 44..47 once (bytes beyond EWs; never clobbered)
    for (int i = lane; i < 4 * ATW_LD; i += 32) Atw[44 * ATW_LD + i] = 0u;
    __syncthreads();

    const int nstrips = NE / EPW;   // 50000
    int gw = blockIdx.x * 8 + wid;
    int nw = gridDim.x * 8;
    for (int s = gw; s < nstrips; s += nw) {
        int e0 = s * EPW;
        __syncwarp();   // prior message EWs/EWf reads done
        // stage A^T (rows k=0..40)
        const float4* s4 = reinterpret_cast<const float4*>(&g_eap[(ll)e0 * FE]);
        #pragma unroll
        for (int j = 0; j < 6; j++) {
            int i4 = lane + 32 * j;
            if (i4 < 164) {
                float4 v = s4[i4];
                int ib = 4 * i4;
                #pragma unroll
                for (int q = 0; q < 4; q++) {
                    int i = ib + q;
                    int r = __float2int_rd((i + 0.5f) * (1.0f / 41.0f));
                    int k = i - 41 * r;
                    Atw[k * ATW_LD + r] = to_tf32((&v.x)[q]);
                }
            }
        }
        // re-zero padding rows 41..43 (clobbered by prior EWs)
        for (int i = lane; i < 3 * ATW_LD; i += 32) Atw[41 * ATW_LD + i] = 0u;
        int sv = (lane < 16) ? g_srcp[e0 + lane] : g_dstp[e0 + lane - 16];
        __syncwarp();

        // ---- f-half: cols 0..63 -> EWf (disjoint from At) ----
        {
            float c[8][4];
            #pragma unroll
            for (int nt = 0; nt < 8; nt++)
                #pragma unroll
                for (int q = 0; q < 4; q++) c[nt][q] = 0.f;
            #pragma unroll
            for (int kk = 0; kk < 6; kk++) {
                uint32_t a0 = Atw[(8 * kk + tig) * ATW_LD + gid];
                uint32_t a1 = Atw[(8 * kk + tig) * ATW_LD + gid + 8];
                uint32_t a2 = Atw[(8 * kk + tig + 4) * ATW_LD + gid];
                uint32_t a3 = Atw[(8 * kk + tig + 4) * ATW_LD + gid + 8];
                #pragma unroll
                for (int nt = 0; nt < 8; nt++) {
                    uint2 b = __ldg(&Bpe[(kk * 16 + nt) * 32 + lane]);
                    mma_tf32(c[nt], a0, a1, a2, a3, b.x, b.y);
                }
            }
            #pragma unroll
            for (int nt = 0; nt < 8; nt++) {
                int col = nt * 8 + 2 * tig;
                float2 bi = *reinterpret_cast<const float2*>(&bias_s[col]);
                *reinterpret_cast<float2*>(&EWf[gid * EW_LDH + col]) =
                    make_float2(c[nt][0] + bi.x, c[nt][1] + bi.y);
                *reinterpret_cast<float2*>(&EWf[(gid + 8) * EW_LDH + col]) =
                    make_float2(c[nt][2] + bi.x, c[nt][3] + bi.y);
            }
        }
        // ---- s-half: cols 64..127 -> EWs (overwrites At AFTER last read) ----
        {
            float c[8][4];
            #pragma unroll
            for (int nt = 0; nt < 8; nt++)
                #pragma unroll
                for (int q = 0; q < 4; q++) c[nt][q] = 0.f;
            #pragma unroll
            for (int kk = 0; kk < 6; kk++) {
                uint32_t a0 = Atw[(8 * kk + tig) * ATW_LD + gid];
                uint32_t a1 = Atw[(8 * kk + tig) * ATW_LD + gid + 8];
                uint32_t a2 = Atw[(8 * kk + tig + 4) * ATW_LD + gid];
                uint32_t a3 = Atw[(8 * kk + tig + 4) * ATW_LD + gid + 8];
                #pragma unroll
                for (int nt = 0; nt < 8; nt++) {
                    uint2 b = __ldg(&Bpe[(kk * 16 + 8 + nt) * 32 + lane]);
                    mma_tf32(c[nt], a0, a1, a2, a3, b.x, b.y);
                }
            }
            __syncwarp();   // all At reads complete before EWs overwrites region
            #pragma unroll
            for (int nt = 0; nt < 8; nt++) {
                int col = nt * 8 + 2 * tig;
                float2 bi = *reinterpret_cast<const float2*>(&bias_s[64 + col]);
                *reinterpret_cast<float2*>(&EWs[gid * EW_LDH + col]) =
                    make_float2(c[nt][0] + bi.x, c[nt][1] + bi.y);
                *reinterpret_cast<float2*>(&EWs[(gid + 8) * EW_LDH + col]) =
                    make_float2(c[nt][2] + bi.x, c[nt][3] + bi.y);
            }
        }
        __syncwarp();

        // ---- message phase: two 8-edge chunks, run compression across chunks ----
        int dprev = -1;
        float fi0 = 0.f, fi1 = 0.f, si0 = 0.f, si1 = 0.f, a0 = 0.f, a1 = 0.f;
        #pragma unroll
        for (int m = 0; m < 2; m++) {
            float2 fj[8], sj[8];
            #pragma unroll
            for (int r = 0; r < 8; r++) {
                int sn = __shfl_sync(0xffffffffu, sv, m * 8 + r);
                fj[r] = *reinterpret_cast<const float2*>(&g_HN[(ll)sn * 256 + 128 + 2 * lane]);
                sj[r] = *reinterpret_cast<const float2*>(&g_HN[(ll)sn * 256 + 192 + 2 * lane]);
            }
            #pragma unroll
            for (int r = 0; r < 8; r++) {
                int e = m * 8 + r;
                int d = __shfl_sync(0xffffffffu, sv, 16 + e);
                if (d != dprev) {
                    if (dprev >= 0) red2(&acc[(ll)dprev * HD + 2 * lane], a0, a1);
                    float2 t0 = *reinterpret_cast<const float2*>(&g_HN[(ll)d * 256 + 2 * lane]);
                    float2 t1 = *reinterpret_cast<const float2*>(&g_HN[(ll)d * 256 + 64 + 2 * lane]);
                    fi0 = t0.x; fi1 = t0.y; si0 = t1.x; si1 = t1.y;
                    a0 = 0.f; a1 = 0.f;
                    dprev = d;
                }
                float2 ef = *reinterpret_cast<const float2*>(&EWf[e * EW_LDH + 2 * lane]);
                float2 es = *reinterpret_cast<const float2*>(&EWs[e * EW_LDH + 2 * lane]);
                a0 += sigmoid_f(ef.x + fi0 + fj[r].x) * softplus_f(es.x + si0 + sj[r].x);
                a1 += sigmoid_f(ef.y + fi1 + fj[r].y) * softplus_f(es.y + si1 + sj[r].y);
            }
        }
        if (dprev >= 0) red2(&acc[(ll)dprev * HD + 2 * lane], a0, a1);
    }
}

// ---------------- BN stats ----------------
__global__ void stats_kernel(int a, const float* __restrict__ buf) {
    __shared__ float s_s[HD], s_q[HD];
    int tid = threadIdx.x;
    if (tid < HD) { s_s[tid] = 0.f; s_q[tid] = 0.f; }
    __syncthreads();
    int col4 = tid & 15;
    float4 ls = make_float4(0.f, 0.f, 0.f, 0.f), lq = ls;
    const float4* acc4 = reinterpret_cast<const float4*>(buf);
    for (int idx4 = blockIdx.x * blockDim.x + tid; idx4 < NN * 16; idx4 += gridDim.x * blockDim.x) {
        float4 v = acc4[idx4];
        ls.x += v.x; lq.x = fmaf(v.x, v.x, lq.x);
        ls.y += v.y; lq.y = fmaf(v.y, v.y, lq.y);
        ls.z += v.z; lq.z = fmaf(v.z, v.z, lq.z);
        ls.w += v.w; lq.w = fmaf(v.w, v.w, lq.w);
    }
    atomicAdd(&s_s[col4 * 4 + 0], ls.x); atomicAdd(&s_q[col4 * 4 + 0], lq.x);
    atomicAdd(&s_s[col4 * 4 + 1], ls.y); atomicAdd(&s_q[col4 * 4 + 1], lq.y);
    atomicAdd(&s_s[col4 * 4 + 2], ls.z); atomicAdd(&s_q[col4 * 4 + 2], lq.z);
    atomicAdd(&s_s[col4 * 4 + 3], ls.w); atomicAdd(&s_q[col4 * 4 + 3], lq.w);
    __syncthreads();
    if (tid < HD) {
        atomicAdd(&g_sum[a * HD + tid], s_s[tid]);
        atomicAdd(&g_sumsq[a * HD + tid], s_q[tid]);
    }
}

// ---------------- final BN + pooling ----------------
__global__ void bn_kernel(const float* __restrict__ gamma, const float* __restrict__ beta,
                          int a, const float* __restrict__ buf,
                          const int* __restrict__ batch) {
    int idx4 = blockIdx.x * blockDim.x + threadIdx.x;
    if (idx4 >= NN * 16) return;
    int col4 = idx4 & 15;
    int node = idx4 >> 4;
    const float invn = 1.0f / (float)NN;
    float4 su = reinterpret_cast<const float4*>(g_sum)[a * 16 + col4];
    float4 sq = reinterpret_cast<const float4*>(g_sumsq)[a * 16 + col4];
    float4 ga = reinterpret_cast<const float4*>(gamma)[col4];
    float4 be = reinterpret_cast<const float4*>(beta)[col4];
    float4 v = reinterpret_cast<const float4*>(buf)[idx4];
    #pragma unroll
    for (int c = 0; c < 4; c++) {
        float mu = (&su.x)[c] * invn;
        float var = fmaxf((&sq.x)[c] * invn - mu * mu, 0.f);
        (&v.x)[c] = ((&v.x)[c] - mu) * rsqrtf(var + BN_EPS) * (&ga.x)[c] + (&be.x)[c];
    }
    int b = batch[node];
    red4(&g_gsum[b * HD + col4 * 4], v);
    if (col4 == 0) atomicAdd(&g_gcnt[b], 1.0f);
}

// ---------------- final MLP ----------------
__global__ void mlp_kernel(const float* __restrict__ W1, const float* __restrict__ b1,
                           const float* __restrict__ W2, const float* __restrict__ b2,
                           const float* __restrict__ Wo, const float* __restrict__ bo,
                           float* __restrict__ out) {
    __shared__ float sW1[HD * HD], sW2[HD * HD], sWo[HD], sb1[HD], sb2[HD];
    int tid = threadIdx.x;
    for (int i = tid; i < HD * HD; i += blockDim.x) { sW1[i] = W1[i]; sW2[i] = W2[i]; }
    if (tid < HD) { sWo[tid] = Wo[tid]; sb1[tid] = b1[tid]; sb2[tid] = b2[tid]; }
    __syncthreads();
    if (tid < NG) {
        float inv = 1.0f / fmaxf(g_gcnt[tid], 1.0f);
        float v[HD], y[HD];
        #pragma unroll
        for (int k = 0; k < HD; k++) v[k] = g_gsum[tid * HD + k] * inv;
        #pragma unroll 1
        for (int j = 0; j < HD; j++) {
            float s = sb1[j];
            #pragma unroll
            for (int k = 0; k < HD; k++) s = fmaf(v[k], sW1[k * HD + j], s);
            y[j] = fmaxf(s, 0.0f) + __logf(1.0f + __expf(-fabsf(s)));
        }
        float o = bo[0];
        #pragma unroll 1
        for (int j = 0; j < HD; j++) {
            float s = sb2[j];
            #pragma unroll
            for (int k = 0; k < HD; k++) s = fmaf(y[k], sW2[k * HD + j], s);
            o = fmaf(fmaxf(s, 0.0f) + __logf(1.0f + __expf(-fabsf(s))), sWo[j], o);
        }
        out[tid] = o;
    }
}

extern "C" void kernel_launch(void* const* d_in, const int* in_sizes, int n_in,
                              void* d_out, int out_size) {
    const float* x         = (const float*)d_in[0];
    const float* edge_attr = (const float*)d_in[1];
    const int*   ei        = (const int*)d_in[2];
    const int*   batch     = (const int*)d_in[3];
    const float* W_emb1    = (const float*)d_in[4];
    const float* b_emb1    = (const float*)d_in[5];
    const float* W_emb2    = (const float*)d_in[6];
    const float* b_emb2    = (const float*)d_in[7];
    const float* Wf        = (const float*)d_in[8];
    const float* bf        = (const float*)d_in[9];
    const float* Ws        = (const float*)d_in[10];
    const float* bs        = (const float*)d_in[11];
    const float* gamma     = (const float*)d_in[12];
    const float* beta      = (const float*)d_in[13];
    const float* W1        = (const float*)d_in[14];
    const float* b1        = (const float*)d_in[15];
    const float* W2        = (const float*)d_in[16];
    const float* b2        = (const float*)d_in[17];
    const float* Wo        = (const float*)d_in[18];
    const float* bo        = (const float*)d_in[19];
    float* out = (float*)d_out;

    float *p_h, *p_acc, *p_bce, *p_Wnode, *p_HN, *p_sum, *p_sumsq;
    uint2* p_Bpe;
    cudaGetSymbolAddress((void**)&p_h, g_h);
    cudaGetSymbolAddress((void**)&p_acc, g_acc);
    cudaGetSymbolAddress((void**)&p_bce, g_bce);
    cudaGetSymbolAddress((void**)&p_Wnode, g_Wnode);
    cudaGetSymbolAddress((void**)&p_HN, g_HN);
    cudaGetSymbolAddress((void**)&p_sum, g_sum);
    cudaGetSymbolAddress((void**)&p_sumsq, g_sumsq);
    cudaGetSymbolAddress((void**)&p_Bpe, g_Bpe);

    // fold weights + zero counters/stats, then prepack edge B fragments
    prep_kernel<<<255, 256>>>(W_emb2, b_emb2, Wf, bf, Ws, bs);
    bp_pack_kernel<<<(NCV * 3072 + 255) / 256, 256>>>();

    // sort edges by dst + permute edge_attr
    hist_kernel<<<(NE + 255) / 256, 256>>>(ei);
    scan1_kernel<<<NBLK, 256>>>();
    scan2_kernel<<<1, 256>>>();
    scan3_kernel<<<NBLK, 256>>>();
    scatter_perm_kernel<<<3200, 256>>>(ei, edge_attr);

    cudaFuncSetAttribute(emb_mma_kernel,
                         cudaFuncAttributeMaxDynamicSharedMemorySize, EM_SMEM);
    cudaFuncSetAttribute(node_mma_kernel,
                         cudaFuncAttributeMaxDynamicSharedMemorySize, ND_SMEM);
    cudaFuncSetAttribute(fused_edge_kernel,
                         cudaFuncAttributeMaxDynamicSharedMemorySize, FE_SMEM);

    // h0 = x @ W_emb1 + b_emb1, dual-stored to g_h and g_acc
    emb_mma_kernel<<<148, 512, EM_SMEM>>>(x, W_emb1, b_emb1);

    // ping-pong raw accumulator: L0->g_acc, L1->g_h, L2->g_acc
    float* rawbuf[3] = { p_acc, p_h, p_acc };
    float* srcbuf[3] = { p_h, p_acc, p_h };

    for (int a = 0; a < NCV; a++) {
        const float* bnsum = (a == 0) ? nullptr : p_sum + (a - 1) * HD;
        const float* bnsq  = (a == 0) ? nullptr : p_sumsq + (a - 1) * HD;
        const float* bngam = (a == 0) ? nullptr : gamma + (a - 1) * HD;
        const float* bnbet = (a == 0) ? nullptr : beta + (a - 1) * HD;
        float* wb = (a == 0) ? nullptr : rawbuf[a];
        node_mma_kernel<<<148, 512, ND_SMEM>>>(srcbuf[a],
                                               p_Wnode + (ll)a * HD * 4 * HD,
                                               p_HN, wb, bnsum, bnsq, bngam, bnbet);
        fused_edge_kernel<<<444, 256, FE_SMEM>>>(rawbuf[a],
                                                 p_Bpe + a * 3072,
                                                 p_bce + a * 2 * HD);
        stats_kernel<<<296, 256>>>(a, rawbuf[a]);
    }

    // final BN (no relu) + pooling from rawbuf[2]
    bn_kernel<<<(NN * 16 + 255) / 256, 256>>>(gamma + 2 * HD, beta + 2 * HD, 2,
                                              rawbuf[2], batch);

    mlp_kernel<<<1, 128>>>(W1, b1, W2, b2, Wo, bo, out);
}

// round 16
// speedup vs baseline: 1.1399x; 1.1399x over previous
#include <cuda_runtime.h>
#include <math.h>
#include <stdint.h>

#define NN 50000      // nodes
#define NE 800000     // edges
#define NG 128        // graphs
#define FX 92         // node feature dim
#define FE 41         // edge feature dim
#define HD 64         // hidden
#define NCV 3         // conv layers
#define BN_EPS 1e-5f
#define NBLK 196      // scan blocks
#define EPW 16        // rows/edges per warp-strip

typedef unsigned long long ull;
typedef long long ll;

// ---------------- device scratch ----------------
__device__ float g_h[NN * HD];
__device__ float g_acc[NN * HD];
__device__ float g_HN[NN * 4 * HD];                   // [N,256]: [f_i|s_i|f_j|s_j]
__device__ float g_Wce[NCV * FE * 2 * HD];
__device__ float g_bce[NCV * 2 * HD];
__device__ float g_Wnode[NCV * HD * 4 * HD];
__device__ float g_sum[NCV * HD];
__device__ float g_sumsq[NCV * HD];
__device__ float g_gsum[NG * HD];
__device__ float g_gcnt[NG];
// sort-by-dst machinery
__device__ int   g_deg[NN];
__device__ int   g_cursor[NN];
__device__ int   g_rp[NN];
__device__ int   g_bsum[256];
__device__ int   g_srcp[NE];
__device__ int   g_dstp[NE];
__device__ float g_eap[(ll)NE * FE];   // permuted edge_attr (row-major, sorted order)

// ---------------- helpers ----------------
__device__ __forceinline__ float sigmoid_f(float x) {
    float t;
    asm("tanh.approx.f32 %0, %1;" : "=f"(t) : "f"(x * 0.5f));
    return fmaf(t, 0.5f, 0.5f);
}
__device__ __forceinline__ float softplus_f(float x) {
    return fmaxf(x, 0.0f) + __logf(1.0f + __expf(-fabsf(x)));
}
__device__ __forceinline__ void red4(float* p, float4 v) {
    asm volatile("red.global.add.v4.f32 [%0], {%1,%2,%3,%4};"
                 :: "l"(p), "f"(v.x), "f"(v.y), "f"(v.z), "f"(v.w) : "memory");
}
__device__ __forceinline__ void red2(float* p, float a, float b) {
    asm volatile("red.global.add.v2.f32 [%0], {%1,%2};"
                 :: "l"(p), "f"(a), "f"(b) : "memory");
}
__device__ __forceinline__ uint32_t to_tf32(float f) {
    uint32_t r; asm("cvt.rna.tf32.f32 %0, %1;" : "=r"(r) : "f"(f)); return r;
}
__device__ __forceinline__ void mma_tf32(float c[4], uint32_t a0, uint32_t a1,
                                         uint32_t a2, uint32_t a3,
                                         uint32_t b0, uint32_t b1) {
    asm volatile(
        "mma.sync.aligned.m16n8k8.row.col.f32.tf32.tf32.f32 "
        "{%0,%1,%2,%3}, {%4,%5,%6,%7}, {%8,%9}, {%0,%1,%2,%3};"
        : "+f"(c[0]), "+f"(c[1]), "+f"(c[2]), "+f"(c[3])
        : "r"(a0), "r"(a1), "r"(a2), "r"(a3), "r"(b0), "r"(b1));
}

// ---------------- prep: fold weights + zero counters/stats ----------------
__global__ void prep_kernel(const float* __restrict__ W_emb2, const float* __restrict__ b_emb2,
                            const float* __restrict__ Wf, const float* __restrict__ bf,
                            const float* __restrict__ Ws, const float* __restrict__ bs) {
    int idx = blockIdx.x * blockDim.x + threadIdx.x;
    const int N_WCE = NCV * FE * 2 * HD;
    const int N_BCE = NCV * 2 * HD;
    const int N_WND = NCV * HD * 4 * HD;
    if (idx < NN) { g_deg[idx] = 0; g_cursor[idx] = 0; }
    if (idx < NCV * HD) { g_sum[idx] = 0.f; g_sumsq[idx] = 0.f; }
    if (idx < NG * HD) g_gsum[idx] = 0.f;
    if (idx < NG) g_gcnt[idx] = 0.f;
    if (idx < N_WCE) {
        int j = idx % (2 * HD);
        int k = (idx / (2 * HD)) % FE;
        int a = idx / (2 * HD * FE);
        const float* Wb = (j < HD) ? Wf : Ws;
        int jj = j & (HD - 1);
        float s = 0.f;
        #pragma unroll 8
        for (int m = 0; m < HD; m++)
            s = fmaf(W_emb2[k * HD + m], Wb[(a * 3 * HD + 2 * HD + m) * HD + jj], s);
        g_Wce[idx] = s;
    } else if (idx < N_WCE + N_BCE) {
        int t = idx - N_WCE;
        int j = t % (2 * HD);
        int a = t / (2 * HD);
        const float* Wb = (j < HD) ? Wf : Ws;
        const float* bb = (j < HD) ? bf : bs;
        int jj = j & (HD - 1);
        float s = bb[a * HD + jj];
        #pragma unroll 8
        for (int m = 0; m < HD; m++)
            s = fmaf(b_emb2[m], Wb[(a * 3 * HD + 2 * HD + m) * HD + jj], s);
        g_bce[t] = s;
    } else if (idx < N_WCE + N_BCE + N_WND) {
        int t = idx - N_WCE - N_BCE;
        int j = t % (4 * HD);
        int m = (t / (4 * HD)) % HD;
        int a = t / (4 * HD * HD);
        int blk = j / HD;                 // 0:f_i 1:s_i 2:f_j 3:s_j
        int jj = j & (HD - 1);
        const float* Wsel = (blk & 1) ? Ws : Wf;
        int roff = (blk >= 2) ? HD : 0;
        g_Wnode[t] = Wsel[(a * 3 * HD + roff + m) * HD + jj];
    }
}

// ---------------- sort by dst ----------------
__global__ void hist_kernel(const int* __restrict__ ei) {
    int e = blockIdx.x * blockDim.x + threadIdx.x;
    if (e < NE) atomicAdd(&g_deg[ei[NE + e]], 1);
}
__global__ void scan1_kernel() {
    __shared__ int s[256];
    int tid = threadIdx.x;
    int i = blockIdx.x * 256 + tid;
    int v = (i < NN) ? g_deg[i] : 0;
    s[tid] = v; __syncthreads();
    #pragma unroll
    for (int off = 1; off < 256; off <<= 1) {
        int t = (tid >= off) ? s[tid - off] : 0;
        __syncthreads();
        s[tid] += t;
        __syncthreads();
    }
    if (i < NN) g_rp[i] = s[tid] - v;
    if (tid == 255) g_bsum[blockIdx.x] = s[255];
}
__global__ void scan2_kernel() {
    __shared__ int s[256];
    int tid = threadIdx.x;
    int v = (tid < NBLK) ? g_bsum[tid] : 0;
    s[tid] = v; __syncthreads();
    #pragma unroll
    for (int off = 1; off < 256; off <<= 1) {
        int t = (tid >= off) ? s[tid - off] : 0;
        __syncthreads();
        s[tid] += t;
        __syncthreads();
    }
    if (tid < NBLK) g_bsum[tid] = s[tid] - v;
}
__global__ void scan3_kernel() {
    int i = blockIdx.x * 256 + threadIdx.x;
    if (i < NN) g_rp[i] += g_bsum[blockIdx.x];
}
// merged scatter + edge_attr permute: warp per edge
__global__ void scatter_perm_kernel(const int* __restrict__ ei, const float* __restrict__ ea) {
    int w = (blockIdx.x * blockDim.x + threadIdx.x) >> 5;
    int lane = threadIdx.x & 31;
    int nw = (gridDim.x * blockDim.x) >> 5;
    for (int e = w; e < NE; e += nw) {
        int pos = 0;
        if (lane == 0) {
            int d = ei[NE + e];
            int s = ei[e];
            pos = g_rp[d] + atomicAdd(&g_cursor[d], 1);
            g_srcp[pos] = s;
            g_dstp[pos] = d;
        }
        pos = __shfl_sync(0xffffffffu, pos, 0);
        for (int k = lane; k < FE; k += 32)
            g_eap[(ll)pos * FE + k] = ea[(ll)e * FE + k];
    }
}

// ---------------- embedding GEMM: mma.sync tf32, warp-autonomous ----------------
#define EM_ATLD 24
#define EM_SMBP 512
#define EM_SMWR (EM_SMBP + 3072 * 8)          // 25088
#define EM_WREG 9216                           // 96*24*4
#define EM_SMEM (EM_SMWR + 16 * EM_WREG)       // 172544

__global__ __launch_bounds__(512, 1) void emb_mma_kernel(
        const float* __restrict__ x, const float* __restrict__ W, const float* __restrict__ b) {
    extern __shared__ char base[];
    float* bias_s = (float*)base;
    uint2* Bp = (uint2*)(base + EM_SMBP);
    int tid = threadIdx.x;
    int lane = tid & 31, wid = tid >> 5;
    int gid = lane >> 2, tig = lane & 3;
    uint32_t* Atw = (uint32_t*)(base + EM_SMWR + wid * EM_WREG);

    if (tid < HD) bias_s[tid] = b[tid];
    for (int i = tid; i < 3072; i += 512) {
        int l = i & 31, nt = (i >> 5) & 7, kk = i >> 8;
        int g = l >> 2, t = l & 3;
        int k0 = 8 * kk + t, k1 = k0 + 4;
        uint32_t b0 = (k0 < FX) ? to_tf32(W[k0 * HD + 8 * nt + g]) : 0u;
        uint32_t b1 = (k1 < FX) ? to_tf32(W[k1 * HD + 8 * nt + g]) : 0u;
        Bp[i] = make_uint2(b0, b1);
    }
    for (int i = lane; i < 4 * EM_ATLD; i += 32) Atw[FX * EM_ATLD + i] = 0u;
    __syncthreads();

    const int nstrips = NN / EPW;   // 3125
    int gw = blockIdx.x * 16 + wid;
    int nw = gridDim.x * 16;
    for (int s = gw; s < nstrips; s += nw) {
        int row0 = s * EPW;
        __syncwarp();
        const float4* s4 = reinterpret_cast<const float4*>(&x[(ll)row0 * FX]);
        #pragma unroll
        for (int j = 0; j < 12; j++) {
            int i4 = lane + 32 * j;
            if (i4 < 368) {
                float4 v = s4[i4];
                int r = __float2int_rd((i4 + 0.5f) * (1.0f / 23.0f));
                int k0 = (i4 - 23 * r) * 4;
                Atw[(k0 + 0) * EM_ATLD + r] = to_tf32(v.x);
                Atw[(k0 + 1) * EM_ATLD + r] = to_tf32(v.y);
                Atw[(k0 + 2) * EM_ATLD + r] = to_tf32(v.z);
                Atw[(k0 + 3) * EM_ATLD + r] = to_tf32(v.w);
            }
        }
        __syncwarp();
        float c[8][4];
        #pragma unroll
        for (int nt = 0; nt < 8; nt++)
            #pragma unroll
            for (int q = 0; q < 4; q++) c[nt][q] = 0.f;
        #pragma unroll
        for (int kk = 0; kk < 12; kk++) {
            uint32_t a0 = Atw[(8 * kk + tig) * EM_ATLD + gid];
            uint32_t a1 = Atw[(8 * kk + tig) * EM_ATLD + gid + 8];
            uint32_t a2 = Atw[(8 * kk + tig + 4) * EM_ATLD + gid];
            uint32_t a3 = Atw[(8 * kk + tig + 4) * EM_ATLD + gid + 8];
            #pragma unroll
            for (int nt = 0; nt < 8; nt++) {
                uint2 bb = Bp[(kk * 8 + nt) * 32 + lane];
                mma_tf32(c[nt], a0, a1, a2, a3, bb.x, bb.y);
            }
        }
        #pragma unroll
        for (int nt = 0; nt < 8; nt++) {
            int col = nt * 8 + 2 * tig;
            float2 bi = *reinterpret_cast<const float2*>(&bias_s[col]);
            float2 v0 = make_float2(c[nt][0] + bi.x, c[nt][1] + bi.y);
            float2 v1 = make_float2(c[nt][2] + bi.x, c[nt][3] + bi.y);
            *reinterpret_cast<float2*>(&g_h[(ll)(row0 + gid) * HD + col]) = v0;
            *reinterpret_cast<float2*>(&g_acc[(ll)(row0 + gid) * HD + col]) = v0;
            *reinterpret_cast<float2*>(&g_h[(ll)(row0 + gid + 8) * HD + col]) = v1;
            *reinterpret_cast<float2*>(&g_acc[(ll)(row0 + gid + 8) * HD + col]) = v1;
        }
    }
}

// ---------------- node GEMM: mma.sync tf32, warp-autonomous, fused BN ----------------
#define ND_ATLD 24
#define ND_SMBP 512
#define ND_SMWR 66048
#define ND_WREG 6144
#define ND_SMEM (ND_SMWR + 16 * ND_WREG)   // 164352

__global__ __launch_bounds__(512, 1) void node_mma_kernel(
        const float* __restrict__ src, const float* __restrict__ Wn,
        float* __restrict__ HN, float* __restrict__ wb,
        const float* __restrict__ bnsum, const float* __restrict__ bnsq,
        const float* __restrict__ bngam, const float* __restrict__ bnbet) {
    extern __shared__ char base[];
    float* scl = (float*)base;
    float* sft = scl + HD;
    uint2* Bp = (uint2*)(base + ND_SMBP);
    int tid = threadIdx.x;
    int lane = tid & 31, wid = tid >> 5;
    int gid = lane >> 2, tig = lane & 3;
    uint32_t* Atw = (uint32_t*)(base + ND_SMWR + wid * ND_WREG);
    int dobn = (bnsum != nullptr);

    if (dobn && tid < HD) {
        const float invn = 1.0f / (float)NN;
        float mu = bnsum[tid] * invn;
        float var = fmaxf(bnsq[tid] * invn - mu * mu, 0.f);
        float sc = rsqrtf(var + BN_EPS) * bngam[tid];
        scl[tid] = sc;
        sft[tid] = bnbet[tid] - mu * sc;
    }
    for (int i = tid; i < 8192; i += 512) {
        int l = i & 31, nt = (i >> 5) & 31, kk = i >> 10;
        int g = l >> 2, t = l & 3;
        Bp[i] = make_uint2(to_tf32(Wn[(8 * kk + t) * 256 + 8 * nt + g]),
                           to_tf32(Wn[(8 * kk + t + 4) * 256 + 8 * nt + g]));
    }
    __syncthreads();

    const int nstrips = NN / EPW;   // 3125
    int gw = blockIdx.x * 16 + wid;
    int nw = gridDim.x * 16;
    for (int s = gw; s < nstrips; s += nw) {
        int row0 = s * EPW;
        __syncwarp();
        for (int i = lane; i < EPW * HD; i += 32) {
            int r = i >> 6, k = i & 63;
            int gr = row0 + r;
            float v = src[(ll)gr * HD + k];
            if (dobn) {
                v = fmaxf(fmaf(v, scl[k], sft[k]), 0.f);
                wb[(ll)gr * HD + k] = v;
            }
            Atw[k * ND_ATLD + r] = to_tf32(v);
        }
        __syncwarp();
        #pragma unroll
        for (int h = 0; h < 2; h++) {
            float c[16][4];
            #pragma unroll
            for (int nt = 0; nt < 16; nt++)
                #pragma unroll
                for (int q = 0; q < 4; q++) c[nt][q] = 0.f;
            #pragma unroll
            for (int kk = 0; kk < 8; kk++) {
                uint32_t a0 = Atw[(8 * kk + tig) * ND_ATLD + gid];
                uint32_t a1 = Atw[(8 * kk + tig) * ND_ATLD + gid + 8];
                uint32_t a2 = Atw[(8 * kk + tig + 4) * ND_ATLD + gid];
                uint32_t a3 = Atw[(8 * kk + tig + 4) * ND_ATLD + gid + 8];
                #pragma unroll
                for (int nt = 0; nt < 16; nt++) {
                    uint2 b = Bp[(kk * 32 + h * 16 + nt) * 32 + lane];
                    mma_tf32(c[nt], a0, a1, a2, a3, b.x, b.y);
                }
            }
            #pragma unroll
            for (int nt = 0; nt < 16; nt++) {
                int col = h * 128 + nt * 8 + 2 * tig;
                *reinterpret_cast<float2*>(&HN[(ll)(row0 + gid) * 256 + col]) =
                    make_float2(c[nt][0], c[nt][1]);
                *reinterpret_cast<float2*>(&HN[(ll)(row0 + gid + 8) * 256 + col]) =
                    make_float2(c[nt][2], c[nt][3]);
            }
        }
    }
}

// ---------------- fused edge kernel: warp-autonomous strips ----------------
#define ATW_LD 24
#define SM_BP2 512
#define SM_WR  25088
#define WREG   8448
#define FE_SMEM (SM_WR + 8 * WREG)   // 92672

__global__ __launch_bounds__(256, 2) void fused_edge_kernel(
        float* __restrict__ acc,
        const float* __restrict__ Wce, const float* __restrict__ bce) {
    extern __shared__ char base[];
    float* bias_s = (float*)(base);
    uint2* Bp = (uint2*)(base + SM_BP2);
    int tid = threadIdx.x;
    int lane = tid & 31, wid = tid >> 5;
    int gid = lane >> 2, tig = lane & 3;
    char* wreg = base + SM_WR + wid * WREG;
    uint32_t* Atw = (uint32_t*)wreg;
    float* EWw = (float*)wreg;

    if (tid < 128) bias_s[tid] = bce[tid];
    for (int i = tid; i < 3072; i += 256) {
        int l = i & 31, nt = (i >> 5) & 15, kk = i >> 9;
        int g = l >> 2, t = l & 3;
        int k0 = 8 * kk + t, k1 = k0 + 4, n = 8 * nt + g;
        uint32_t b0 = (k0 < FE) ? to_tf32(Wce[k0 * 128 + n]) : 0u;
        uint32_t b1 = (k1 < FE) ? to_tf32(Wce[k1 * 128 + n]) : 0u;
        Bp[i] = make_uint2(b0, b1);
    }
    __syncthreads();

    const int nstrips = NE / EPW;   // 50000
    int gw = blockIdx.x * 8 + wid;
    int nw = gridDim.x * 8;
    for (int s = gw; s < nstrips; s += nw) {
        int e0 = s * EPW;
        __syncwarp();
        const float4* s4 = reinterpret_cast<const float4*>(&g_eap[(ll)e0 * FE]);
        #pragma unroll
        for (int j = 0; j < 6; j++) {
            int i4 = lane + 32 * j;
            if (i4 < 164) {
                float4 v = s4[i4];
                int ib = 4 * i4;
                #pragma unroll
                for (int q = 0; q < 4; q++) {
                    int i = ib + q;
                    int r = __float2int_rd((i + 0.5f) * (1.0f / 41.0f));
                    int k = i - 41 * r;
                    Atw[k * ATW_LD + r] = to_tf32((&v.x)[q]);
                }
            }
        }
        for (int i = lane; i < 7 * ATW_LD; i += 32)
            Atw[FE * ATW_LD + i] = 0u;
        int sv = (lane < 16) ? g_srcp[e0 + lane] : g_dstp[e0 + lane - 16];
        __syncwarp();

        float c[16][4];
        #pragma unroll
        for (int nt = 0; nt < 16; nt++)
            #pragma unroll
            for (int q = 0; q < 4; q++) c[nt][q] = 0.f;
        #pragma unroll
        for (int kk = 0; kk < 6; kk++) {
            uint32_t a0 = Atw[(8 * kk + tig) * ATW_LD + gid];
            uint32_t a1 = Atw[(8 * kk + tig) * ATW_LD + gid + 8];
            uint32_t a2 = Atw[(8 * kk + tig + 4) * ATW_LD + gid];
            uint32_t a3 = Atw[(8 * kk + tig + 4) * ATW_LD + gid + 8];
            #pragma unroll
            for (int nt = 0; nt < 16; nt++) {
                uint2 b = Bp[(kk * 16 + nt) * 32 + lane];
                mma_tf32(c[nt], a0, a1, a2, a3, b.x, b.y);
            }
        }
        __syncwarp();

        #pragma unroll
        for (int nt = 0; nt < 16; nt++) {
            float2 bi = *reinterpret_cast<const float2*>(&bias_s[nt * 8 + 2 * tig]);
            *reinterpret_cast<float2*>(&EWw[gid * 132 + nt * 8 + 2 * tig]) =
                make_float2(c[nt][0] + bi.x, c[nt][1] + bi.y);
            *reinterpret_cast<float2*>(&EWw[(gid + 8) * 132 + nt * 8 + 2 * tig]) =
                make_float2(c[nt][2] + bi.x, c[nt][3] + bi.y);
        }
        __syncwarp();

        float2 fj[16], sj[16];
        #pragma unroll
        for (int r = 0; r < 16; r++) {
            int sn = __shfl_sync(0xffffffffu, sv, r);
            fj[r] = *reinterpret_cast<const float2*>(&g_HN[(ll)sn * 256 + 128 + 2 * lane]);
            sj[r] = *reinterpret_cast<const float2*>(&g_HN[(ll)sn * 256 + 192 + 2 * lane]);
        }
        int dprev = -1;
        float fi0 = 0.f, fi1 = 0.f, si0 = 0.f, si1 = 0.f, a0 = 0.f, a1 = 0.f;
        #pragma unroll
        for (int r = 0; r < 16; r++) {
            int d = __shfl_sync(0xffffffffu, sv, 16 + r);
            if (d != dprev) {
                if (dprev >= 0) red2(&acc[(ll)dprev * HD + 2 * lane], a0, a1);
                float2 t0 = *reinterpret_cast<const float2*>(&g_HN[(ll)d * 256 + 2 * lane]);
                float2 t1 = *reinterpret_cast<const float2*>(&g_HN[(ll)d * 256 + 64 + 2 * lane]);
                fi0 = t0.x; fi1 = t0.y; si0 = t1.x; si1 = t1.y;
                a0 = 0.f; a1 = 0.f;
                dprev = d;
            }
            float2 ef = *reinterpret_cast<const float2*>(&EWw[r * 132 + 2 * lane]);
            float2 es = *reinterpret_cast<const float2*>(&EWw[r * 132 + 64 + 2 * lane]);
            a0 += sigmoid_f(ef.x + fi0 + fj[r].x) * softplus_f(es.x + si0 + sj[r].x);
            a1 += sigmoid_f(ef.y + fi1 + fj[r].y) * softplus_f(es.y + si1 + sj[r].y);
        }
        if (dprev >= 0) red2(&acc[(ll)dprev * HD + 2 * lane], a0, a1);
    }
}

// ---------------- BN stats ----------------
__global__ void stats_kernel(int a, const float* __restrict__ buf) {
    __shared__ float s_s[HD], s_q[HD];
    int tid = threadIdx.x;
    if (tid < HD) { s_s[tid] = 0.f; s_q[tid] = 0.f; }
    __syncthreads();
    int col4 = tid & 15;
    float4 ls = make_float4(0.f, 0.f, 0.f, 0.f), lq = ls;
    const float4* acc4 = reinterpret_cast<const float4*>(buf);
    for (int idx4 = blockIdx.x * blockDim.x + tid; idx4 < NN * 16; idx4 += gridDim.x * blockDim.x) {
        float4 v = acc4[idx4];
        ls.x += v.x; lq.x = fmaf(v.x, v.x, lq.x);
        ls.y += v.y; lq.y = fmaf(v.y, v.y, lq.y);
        ls.z += v.z; lq.z = fmaf(v.z, v.z, lq.z);
        ls.w += v.w; lq.w = fmaf(v.w, v.w, lq.w);
    }
    atomicAdd(&s_s[col4 * 4 + 0], ls.x); atomicAdd(&s_q[col4 * 4 + 0], lq.x);
    atomicAdd(&s_s[col4 * 4 + 1], ls.y); atomicAdd(&s_q[col4 * 4 + 1], lq.y);
    atomicAdd(&s_s[col4 * 4 + 2], ls.z); atomicAdd(&s_q[col4 * 4 + 2], lq.z);
    atomicAdd(&s_s[col4 * 4 + 3], ls.w); atomicAdd(&s_q[col4 * 4 + 3], lq.w);
    __syncthreads();
    if (tid < HD) {
        atomicAdd(&g_sum[a * HD + tid], s_s[tid]);
        atomicAdd(&g_sumsq[a * HD + tid], s_q[tid]);
    }
}

// ---------------- final BN + pooling ----------------
__global__ void bn_kernel(const float* __restrict__ gamma, const float* __restrict__ beta,
                          int a, const float* __restrict__ buf,
                          const int* __restrict__ batch) {
    int idx4 = blockIdx.x * blockDim.x + threadIdx.x;
    if (idx4 >= NN * 16) return;
    int col4 = idx4 & 15;
    int node = idx4 >> 4;
    const float invn = 1.0f / (float)NN;
    float4 su = reinterpret_cast<const float4*>(g_sum)[a * 16 + col4];
    float4 sq = reinterpret_cast<const float4*>(g_sumsq)[a * 16 + col4];
    float4 ga = reinterpret_cast<const float4*>(gamma)[col4];
    float4 be = reinterpret_cast<const float4*>(beta)[col4];
    float4 v = reinterpret_cast<const float4*>(buf)[idx4];
    #pragma unroll
    for (int c = 0; c < 4; c++) {
        float mu = (&su.x)[c] * invn;
        float var = fmaxf((&sq.x)[c] * invn - mu * mu, 0.f);
        (&v.x)[c] = ((&v.x)[c] - mu) * rsqrtf(var + BN_EPS) * (&ga.x)[c] + (&be.x)[c];
    }
    int b = batch[node];
    red4(&g_gsum[b * HD + col4 * 4], v);
    if (col4 == 0) atomicAdd(&g_gcnt[b], 1.0f);
}

// ---------------- final MLP ----------------
__global__ void mlp_kernel(const float* __restrict__ W1, const float* __restrict__ b1,
                           const float* __restrict__ W2, const float* __restrict__ b2,
                           const float* __restrict__ Wo, const float* __restrict__ bo,
                           float* __restrict__ out) {
    __shared__ float sW1[HD * HD], sW2[HD * HD], sWo[HD], sb1[HD], sb2[HD];
    int tid = threadIdx.x;
    for (int i = tid; i < HD * HD; i += blockDim.x) { sW1[i] = W1[i]; sW2[i] = W2[i]; }
    if (tid < HD) { sWo[tid] = Wo[tid]; sb1[tid] = b1[tid]; sb2[tid] = b2[tid]; }
    __syncthreads();
    if (tid < NG) {
        float inv = 1.0f / fmaxf(g_gcnt[tid], 1.0f);
        float v[HD], y[HD];
        #pragma unroll
        for (int k = 0; k < HD; k++) v[k] = g_gsum[tid * HD + k] * inv;
        #pragma unroll 1
        for (int j = 0; j < HD; j++) {
            float s = sb1[j];
            #pragma unroll
            for (int k = 0; k < HD; k++) s = fmaf(v[k], sW1[k * HD + j], s);
            y[j] = fmaxf(s, 0.0f) + __logf(1.0f + __expf(-fabsf(s)));
        }
        float o = bo[0];
        #pragma unroll 1
        for (int j = 0; j < HD; j++) {
            float s = sb2[j];
            #pragma unroll
            for (int k = 0; k < HD; k++) s = fmaf(y[k], sW2[k * HD + j], s);
            o = fmaf(fmaxf(s, 0.0f) + __logf(1.0f + __expf(-fabsf(s))), sWo[j], o);
        }
        out[tid] = o;
    }
}

extern "C" void kernel_launch(void* const* d_in, const int* in_sizes, int n_in,
                              void* d_out, int out_size) {
    const float* x         = (const float*)d_in[0];
    const float* edge_attr = (const float*)d_in[1];
    const int*   ei        = (const int*)d_in[2];
    const int*   batch     = (const int*)d_in[3];
    const float* W_emb1    = (const float*)d_in[4];
    const float* b_emb1    = (const float*)d_in[5];
    const float* W_emb2    = (const float*)d_in[6];
    const float* b_emb2    = (const float*)d_in[7];
    const float* Wf        = (const float*)d_in[8];
    const float* bf        = (const float*)d_in[9];
    const float* Ws        = (const float*)d_in[10];
    const float* bs        = (const float*)d_in[11];
    const float* gamma     = (const float*)d_in[12];
    const float* beta      = (const float*)d_in[13];
    const float* W1        = (const float*)d_in[14];
    const float* b1        = (const float*)d_in[15];
    const float* W2        = (const float*)d_in[16];
    const float* b2        = (const float*)d_in[17];
    const float* Wo        = (const float*)d_in[18];
    const float* bo        = (const float*)d_in[19];
    float* out = (float*)d_out;

    float *p_h, *p_acc, *p_Wce, *p_bce, *p_Wnode, *p_HN, *p_sum, *p_sumsq;
    cudaGetSymbolAddress((void**)&p_h, g_h);
    cudaGetSymbolAddress((void**)&p_acc, g_acc);
    cudaGetSymbolAddress((void**)&p_Wce, g_Wce);
    cudaGetSymbolAddress((void**)&p_bce, g_bce);
    cudaGetSymbolAddress((void**)&p_Wnode, g_Wnode);
    cudaGetSymbolAddress((void**)&p_HN, g_HN);
    cudaGetSymbolAddress((void**)&p_sum, g_sum);
    cudaGetSymbolAddress((void**)&p_sumsq, g_sumsq);

    // fold weights + zero counters/stats (merged)
    prep_kernel<<<255, 256>>>(W_emb2, b_emb2, Wf, bf, Ws, bs);

    // sort edges by dst + permute edge_attr (merged scatter)
    hist_kernel<<<(NE + 255) / 256, 256>>>(ei);
    scan1_kernel<<<NBLK, 256>>>();
    scan2_kernel<<<1, 256>>>();
    scan3_kernel<<<NBLK, 256>>>();
    scatter_perm_kernel<<<6400, 256>>>(ei, edge_attr);

    cudaFuncSetAttribute(emb_mma_kernel,
                         cudaFuncAttributeMaxDynamicSharedMemorySize, EM_SMEM);
    cudaFuncSetAttribute(node_mma_kernel,
                         cudaFuncAttributeMaxDynamicSharedMemorySize, ND_SMEM);
    cudaFuncSetAttribute(fused_edge_kernel,
                         cudaFuncAttributeMaxDynamicSharedMemorySize, FE_SMEM);

    // h0 = x @ W_emb1 + b_emb1, dual-stored to g_h and g_acc (tensor path)
    emb_mma_kernel<<<148, 512, EM_SMEM>>>(x, W_emb1, b_emb1);

    // ping-pong raw accumulator: L0->g_acc, L1->g_h, L2->g_acc
    float* rawbuf[3] = { p_acc, p_h, p_acc };
    float* srcbuf[3] = { p_h, p_acc, p_h };

    for (int a = 0; a < NCV; a++) {
        const float* bnsum = (a == 0) ? nullptr : p_sum + (a - 1) * HD;
        const float* bnsq  = (a == 0) ? nullptr : p_sumsq + (a - 1) * HD;
        const float* bngam = (a == 0) ? nullptr : gamma + (a - 1) * HD;
        const float* bnbet = (a == 0) ? nullptr : beta + (a - 1) * HD;
        float* wb = (a == 0) ? nullptr : rawbuf[a];
        node_mma_kernel<<<148, 512, ND_SMEM>>>(srcbuf[a],
                                               p_Wnode + (ll)a * HD * 4 * HD,
                                               p_HN, wb, bnsum, bnsq, bngam, bnbet);
        fused_edge_kernel<<<296, 256, FE_SMEM>>>(rawbuf[a],
                                                 p_Wce + a * FE * 2 * HD,
                                                 p_bce + a * 2 * HD);
        stats_kernel<<<296, 256>>>(a, rawbuf[a]);
    }

    // final BN (no relu) + pooling from rawbuf[2]
    bn_kernel<<<(NN * 16 + 255) / 256, 256>>>(gamma + 2 * HD, beta + 2 * HD, 2,
                                              rawbuf[2], batch);

    mlp_kernel<<<1, 128>>>(W1, b1, W2, b2, Wo, bo, out);
}

// round 17
// speedup vs baseline: 1.1675x; 1.0242x over previous
#include <cuda_runtime.h>
#include <math.h>
#include <stdint.h>

#define NN 50000      // nodes
#define NE 800000     // edges
#define NG 128        // graphs
#define FX 92         // node feature dim
#define FE 41         // edge feature dim
#define HD 64         // hidden
#define NCV 3         // conv layers
#define BN_EPS 1e-5f
#define NBLK 196      // scan blocks
#define EPW 16        // rows/edges per warp-strip

typedef unsigned long long ull;
typedef long long ll;

// ---------------- device scratch ----------------
__device__ float    g_h[NN * HD];
__device__ float    g_acc[NN * HD];
__device__ uint32_t g_HN[NN * 128];                   // [N,256] bf16 as 128 bf16x2: [f_i|s_i|f_j|s_j]
__device__ float    g_Wce[NCV * FE * 2 * HD];
__device__ float    g_bce[NCV * 2 * HD];
__device__ float    g_Wnode[NCV * HD * 4 * HD];
__device__ float    g_sum[NCV * HD];
__device__ float    g_sumsq[NCV * HD];
__device__ float    g_gsum[NG * HD];
__device__ float    g_gcnt[NG];
// sort-by-dst machinery
__device__ int      g_deg[NN];
__device__ int      g_cursor[NN];
__device__ int      g_rp[NN];
__device__ int      g_bsum[256];
__device__ int      g_srcp[NE];
__device__ int      g_dstp[NE];
__device__ float    g_eap[(ll)NE * FE];   // permuted edge_attr (sorted order)

// ---------------- helpers ----------------
__device__ __forceinline__ float sigmoid_f(float x) {
    float t;
    asm("tanh.approx.f32 %0, %1;" : "=f"(t) : "f"(x * 0.5f));
    return fmaf(t, 0.5f, 0.5f);
}
__device__ __forceinline__ float softplus_f(float x) {
    return fmaxf(x, 0.0f) + __logf(1.0f + __expf(-fabsf(x)));
}
__device__ __forceinline__ void red4(float* p, float4 v) {
    asm volatile("red.global.add.v4.f32 [%0], {%1,%2,%3,%4};"
                 :: "l"(p), "f"(v.x), "f"(v.y), "f"(v.z), "f"(v.w) : "memory");
}
__device__ __forceinline__ void red2(float* p, float a, float b) {
    asm volatile("red.global.add.v2.f32 [%0], {%1,%2};"
                 :: "l"(p), "f"(a), "f"(b) : "memory");
}
__device__ __forceinline__ uint32_t to_tf32(float f) {
    uint32_t r; asm("cvt.rna.tf32.f32 %0, %1;" : "=r"(r) : "f"(f)); return r;
}
// pack (lo=c0, hi=c1) into bf16x2
__device__ __forceinline__ uint32_t pack_bf2(float c0, float c1) {
    uint32_t d;
    asm("cvt.rn.bf16x2.f32 %0, %1, %2;" : "=r"(d) : "f"(c1), "f"(c0));
    return d;
}
// expand bf16x2 -> float2 (lo, hi)
__device__ __forceinline__ float2 bf2f(uint32_t u) {
    float2 r;
    r.x = __uint_as_float(u << 16);
    r.y = __uint_as_float(u & 0xffff0000u);
    return r;
}
__device__ __forceinline__ void mma_tf32(float c[4], uint32_t a0, uint32_t a1,
                                         uint32_t a2, uint32_t a3,
                                         uint32_t b0, uint32_t b1) {
    asm volatile(
        "mma.sync.aligned.m16n8k8.row.col.f32.tf32.tf32.f32 "
        "{%0,%1,%2,%3}, {%4,%5,%6,%7}, {%8,%9}, {%0,%1,%2,%3};"
        : "+f"(c[0]), "+f"(c[1]), "+f"(c[2]), "+f"(c[3])
        : "r"(a0), "r"(a1), "r"(a2), "r"(a3), "r"(b0), "r"(b1));
}

// ---------------- prep: fold weights + zero counters/stats ----------------
__global__ void prep_kernel(const float* __restrict__ W_emb2, const float* __restrict__ b_emb2,
                            const float* __restrict__ Wf, const float* __restrict__ bf,
                            const float* __restrict__ Ws, const float* __restrict__ bs) {
    int idx = blockIdx.x * blockDim.x + threadIdx.x;
    const int N_WCE = NCV * FE * 2 * HD;
    const int N_BCE = NCV * 2 * HD;
    const int N_WND = NCV * HD * 4 * HD;
    if (idx < NN) { g_deg[idx] = 0; g_cursor[idx] = 0; }
    if (idx < NCV * HD) { g_sum[idx] = 0.f; g_sumsq[idx] = 0.f; }
    if (idx < NG * HD) g_gsum[idx] = 0.f;
    if (idx < NG) g_gcnt[idx] = 0.f;
    if (idx < N_WCE) {
        int j = idx % (2 * HD);
        int k = (idx / (2 * HD)) % FE;
        int a = idx / (2 * HD * FE);
        const float* Wb = (j < HD) ? Wf : Ws;
        int jj = j & (HD - 1);
        float s = 0.f;
        #pragma unroll 8
        for (int m = 0; m < HD; m++)
            s = fmaf(W_emb2[k * HD + m], Wb[(a * 3 * HD + 2 * HD + m) * HD + jj], s);
        g_Wce[idx] = s;
    } else if (idx < N_WCE + N_BCE) {
        int t = idx - N_WCE;
        int j = t % (2 * HD);
        int a = t / (2 * HD);
        const float* Wb = (j < HD) ? Wf : Ws;
        const float* bb = (j < HD) ? bf : bs;
        int jj = j & (HD - 1);
        float s = bb[a * HD + jj];
        #pragma unroll 8
        for (int m = 0; m < HD; m++)
            s = fmaf(b_emb2[m], Wb[(a * 3 * HD + 2 * HD + m) * HD + jj], s);
        g_bce[t] = s;
    } else if (idx < N_WCE + N_BCE + N_WND) {
        int t = idx - N_WCE - N_BCE;
        int j = t % (4 * HD);
        int m = (t / (4 * HD)) % HD;
        int a = t / (4 * HD * HD);
        int blk = j / HD;                 // 0:f_i 1:s_i 2:f_j 3:s_j
        int jj = j & (HD - 1);
        const float* Wsel = (blk & 1) ? Ws : Wf;
        int roff = (blk >= 2) ? HD : 0;
        g_Wnode[t] = Wsel[(a * 3 * HD + roff + m) * HD + jj];
    }
}

// ---------------- sort by dst ----------------
__global__ void hist_kernel(const int* __restrict__ ei) {
    int e = blockIdx.x * blockDim.x + threadIdx.x;
    if (e < NE) atomicAdd(&g_deg[ei[NE + e]], 1);
}
__global__ void scan1_kernel() {
    __shared__ int s[256];
    int tid = threadIdx.x;
    int i = blockIdx.x * 256 + tid;
    int v = (i < NN) ? g_deg[i] : 0;
    s[tid] = v; __syncthreads();
    #pragma unroll
    for (int off = 1; off < 256; off <<= 1) {
        int t = (tid >= off) ? s[tid - off] : 0;
        __syncthreads();
        s[tid] += t;
        __syncthreads();
    }
    if (i < NN) g_rp[i] = s[tid] - v;
    if (tid == 255) g_bsum[blockIdx.x] = s[255];
}
__global__ void scan2_kernel() {
    __shared__ int s[256];
    int tid = threadIdx.x;
    int v = (tid < NBLK) ? g_bsum[tid] : 0;
    s[tid] = v; __syncthreads();
    #pragma unroll
    for (int off = 1; off < 256; off <<= 1) {
        int t = (tid >= off) ? s[tid - off] : 0;
        __syncthreads();
        s[tid] += t;
        __syncthreads();
    }
    if (tid < NBLK) g_bsum[tid] = s[tid] - v;
}
__global__ void scan3_kernel() {
    int i = blockIdx.x * 256 + threadIdx.x;
    if (i < NN) g_rp[i] += g_bsum[blockIdx.x];
}
__global__ void scatter_perm_kernel(const int* __restrict__ ei, const float* __restrict__ ea) {
    int w = (blockIdx.x * blockDim.x + threadIdx.x) >> 5;
    int lane = threadIdx.x & 31;
    int nw = (gridDim.x * blockDim.x) >> 5;
    for (int e = w; e < NE; e += nw) {
        int pos = 0;
        if (lane == 0) {
            int d = ei[NE + e];
            int s = ei[e];
            pos = g_rp[d] + atomicAdd(&g_cursor[d], 1);
            g_srcp[pos] = s;
            g_dstp[pos] = d;
        }
        pos = __shfl_sync(0xffffffffu, pos, 0);
        for (int k = lane; k < FE; k += 32)
            g_eap[(ll)pos * FE + k] = ea[(ll)e * FE + k];
    }
}

// ---------------- embedding GEMM: mma.sync tf32, warp-autonomous ----------------
#define EM_ATLD 24
#define EM_SMBP 512
#define EM_SMWR (EM_SMBP + 3072 * 8)          // 25088
#define EM_WREG 9216
#define EM_SMEM (EM_SMWR + 16 * EM_WREG)       // 172544

__global__ __launch_bounds__(512, 1) void emb_mma_kernel(
        const float* __restrict__ x, const float* __restrict__ W, const float* __restrict__ b) {
    extern __shared__ char base[];
    float* bias_s = (float*)base;
    uint2* Bp = (uint2*)(base + EM_SMBP);
    int tid = threadIdx.x;
    int lane = tid & 31, wid = tid >> 5;
    int gid = lane >> 2, tig = lane & 3;
    uint32_t* Atw = (uint32_t*)(base + EM_SMWR + wid * EM_WREG);

    if (tid < HD) bias_s[tid] = b[tid];
    for (int i = tid; i < 3072; i += 512) {
        int l = i & 31, nt = (i >> 5) & 7, kk = i >> 8;
        int g = l >> 2, t = l & 3;
        int k0 = 8 * kk + t, k1 = k0 + 4;
        uint32_t b0 = (k0 < FX) ? to_tf32(W[k0 * HD + 8 * nt + g]) : 0u;
        uint32_t b1 = (k1 < FX) ? to_tf32(W[k1 * HD + 8 * nt + g]) : 0u;
        Bp[i] = make_uint2(b0, b1);
    }
    for (int i = lane; i < 4 * EM_ATLD; i += 32) Atw[FX * EM_ATLD + i] = 0u;
    __syncthreads();

    const int nstrips = NN / EPW;
    int gw = blockIdx.x * 16 + wid;
    int nw = gridDim.x * 16;
    for (int s = gw; s < nstrips; s += nw) {
        int row0 = s * EPW;
        __syncwarp();
        const float4* s4 = reinterpret_cast<const float4*>(&x[(ll)row0 * FX]);
        #pragma unroll
        for (int j = 0; j < 12; j++) {
            int i4 = lane + 32 * j;
            if (i4 < 368) {
                float4 v = s4[i4];
                int r = __float2int_rd((i4 + 0.5f) * (1.0f / 23.0f));
                int k0 = (i4 - 23 * r) * 4;
                Atw[(k0 + 0) * EM_ATLD + r] = to_tf32(v.x);
                Atw[(k0 + 1) * EM_ATLD + r] = to_tf32(v.y);
                Atw[(k0 + 2) * EM_ATLD + r] = to_tf32(v.z);
                Atw[(k0 + 3) * EM_ATLD + r] = to_tf32(v.w);
            }
        }
        __syncwarp();
        float c[8][4];
        #pragma unroll
        for (int nt = 0; nt < 8; nt++)
            #pragma unroll
            for (int q = 0; q < 4; q++) c[nt][q] = 0.f;
        #pragma unroll
        for (int kk = 0; kk < 12; kk++) {
            uint32_t a0 = Atw[(8 * kk + tig) * EM_ATLD + gid];
            uint32_t a1 = Atw[(8 * kk + tig) * EM_ATLD + gid + 8];
            uint32_t a2 = Atw[(8 * kk + tig + 4) * EM_ATLD + gid];
            uint32_t a3 = Atw[(8 * kk + tig + 4) * EM_ATLD + gid + 8];
            #pragma unroll
            for (int nt = 0; nt < 8; nt++) {
                uint2 bb = Bp[(kk * 8 + nt) * 32 + lane];
                mma_tf32(c[nt], a0, a1, a2, a3, bb.x, bb.y);
            }
        }
        #pragma unroll
        for (int nt = 0; nt < 8; nt++) {
            int col = nt * 8 + 2 * tig;
            float2 bi = *reinterpret_cast<const float2*>(&bias_s[col]);
            float2 v0 = make_float2(c[nt][0] + bi.x, c[nt][1] + bi.y);
            float2 v1 = make_float2(c[nt][2] + bi.x, c[nt][3] + bi.y);
            *reinterpret_cast<float2*>(&g_h[(ll)(row0 + gid) * HD + col]) = v0;
            *reinterpret_cast<float2*>(&g_acc[(ll)(row0 + gid) * HD + col]) = v0;
            *reinterpret_cast<float2*>(&g_h[(ll)(row0 + gid + 8) * HD + col]) = v1;
            *reinterpret_cast<float2*>(&g_acc[(ll)(row0 + gid + 8) * HD + col]) = v1;
        }
    }
}

// ---------------- node GEMM: mma.sync tf32, fused BN, bf16 HN output ----------------
#define ND_ATLD 24
#define ND_SMBP 512
#define ND_SMWR 66048
#define ND_WREG 6144
#define ND_SMEM (ND_SMWR + 16 * ND_WREG)   // 164352

__global__ __launch_bounds__(512, 1) void node_mma_kernel(
        const float* __restrict__ src, const float* __restrict__ Wn,
        uint32_t* __restrict__ HN, float* __restrict__ wb,
        const float* __restrict__ bnsum, const float* __restrict__ bnsq,
        const float* __restrict__ bngam, const float* __restrict__ bnbet) {
    extern __shared__ char base[];
    float* scl = (float*)base;
    float* sft = scl + HD;
    uint2* Bp = (uint2*)(base + ND_SMBP);
    int tid = threadIdx.x;
    int lane = tid & 31, wid = tid >> 5;
    int gid = lane >> 2, tig = lane & 3;
    uint32_t* Atw = (uint32_t*)(base + ND_SMWR + wid * ND_WREG);
    int dobn = (bnsum != nullptr);

    if (dobn && tid < HD) {
        const float invn = 1.0f / (float)NN;
        float mu = bnsum[tid] * invn;
        float var = fmaxf(bnsq[tid] * invn - mu * mu, 0.f);
        float sc = rsqrtf(var + BN_EPS) * bngam[tid];
        scl[tid] = sc;
        sft[tid] = bnbet[tid] - mu * sc;
    }
    for (int i = tid; i < 8192; i += 512) {
        int l = i & 31, nt = (i >> 5) & 31, kk = i >> 10;
        int g = l >> 2, t = l & 3;
        Bp[i] = make_uint2(to_tf32(Wn[(8 * kk + t) * 256 + 8 * nt + g]),
                           to_tf32(Wn[(8 * kk + t + 4) * 256 + 8 * nt + g]));
    }
    __syncthreads();

    const int nstrips = NN / EPW;
    int gw = blockIdx.x * 16 + wid;
    int nw = gridDim.x * 16;
    for (int s = gw; s < nstrips; s += nw) {
        int row0 = s * EPW;
        __syncwarp();
        for (int i = lane; i < EPW * HD; i += 32) {
            int r = i >> 6, k = i & 63;
            int gr = row0 + r;
            float v = src[(ll)gr * HD + k];
            if (dobn) {
                v = fmaxf(fmaf(v, scl[k], sft[k]), 0.f);
                wb[(ll)gr * HD + k] = v;
            }
            Atw[k * ND_ATLD + r] = to_tf32(v);
        }
        __syncwarp();
        #pragma unroll
        for (int h = 0; h < 2; h++) {
            float c[16][4];
            #pragma unroll
            for (int nt = 0; nt < 16; nt++)
                #pragma unroll
                for (int q = 0; q < 4; q++) c[nt][q] = 0.f;
            #pragma unroll
            for (int kk = 0; kk < 8; kk++) {
                uint32_t a0 = Atw[(8 * kk + tig) * ND_ATLD + gid];
                uint32_t a1 = Atw[(8 * kk + tig) * ND_ATLD + gid + 8];
                uint32_t a2 = Atw[(8 * kk + tig + 4) * ND_ATLD + gid];
                uint32_t a3 = Atw[(8 * kk + tig + 4) * ND_ATLD + gid + 8];
                #pragma unroll
                for (int nt = 0; nt < 16; nt++) {
                    uint2 b = Bp[(kk * 32 + h * 16 + nt) * 32 + lane];
                    mma_tf32(c[nt], a0, a1, a2, a3, b.x, b.y);
                }
            }
            #pragma unroll
            for (int nt = 0; nt < 16; nt++) {
                int p = h * 64 + nt * 4 + tig;        // bf16x2 pair index (col = 2p)
                HN[(ll)(row0 + gid) * 128 + p] = pack_bf2(c[nt][0], c[nt][1]);
                HN[(ll)(row0 + gid + 8) * 128 + p] = pack_bf2(c[nt][2], c[nt][3]);
            }
        }
    }
}

// ---------------- fused edge kernel: warp-autonomous strips, bf16 gathers ----------------
#define ATW_LD 24
#define SM_BP2 512
#define SM_WR  25088
#define WREG   8448
#define FE_SMEM (SM_WR + 8 * WREG)   // 92672

__global__ __launch_bounds__(256, 2) void fused_edge_kernel(
        float* __restrict__ acc,
        const float* __restrict__ Wce, const float* __restrict__ bce) {
    extern __shared__ char base[];
    float* bias_s = (float*)(base);
    uint2* Bp = (uint2*)(base + SM_BP2);
    int tid = threadIdx.x;
    int lane = tid & 31, wid = tid >> 5;
    int gid = lane >> 2, tig = lane & 3;
    char* wreg = base + SM_WR + wid * WREG;
    uint32_t* Atw = (uint32_t*)wreg;
    float* EWw = (float*)wreg;

    if (tid < 128) bias_s[tid] = bce[tid];
    for (int i = tid; i < 3072; i += 256) {
        int l = i & 31, nt = (i >> 5) & 15, kk = i >> 9;
        int g = l >> 2, t = l & 3;
        int k0 = 8 * kk + t, k1 = k0 + 4, n = 8 * nt + g;
        uint32_t b0 = (k0 < FE) ? to_tf32(Wce[k0 * 128 + n]) : 0u;
        uint32_t b1 = (k1 < FE) ? to_tf32(Wce[k1 * 128 + n]) : 0u;
        Bp[i] = make_uint2(b0, b1);
    }
    __syncthreads();

    const int nstrips = NE / EPW;   // 50000
    int gw = blockIdx.x * 8 + wid;
    int nw = gridDim.x * 8;
    for (int s = gw; s < nstrips; s += nw) {
        int e0 = s * EPW;
        __syncwarp();
        const float4* s4 = reinterpret_cast<const float4*>(&g_eap[(ll)e0 * FE]);
        #pragma unroll
        for (int j = 0; j < 6; j++) {
            int i4 = lane + 32 * j;
            if (i4 < 164) {
                float4 v = s4[i4];
                int ib = 4 * i4;
                #pragma unroll
                for (int q = 0; q < 4; q++) {
                    int i = ib + q;
                    int r = __float2int_rd((i + 0.5f) * (1.0f / 41.0f));
                    int k = i - 41 * r;
                    Atw[k * ATW_LD + r] = to_tf32((&v.x)[q]);
                }
            }
        }
        for (int i = lane; i < 7 * ATW_LD; i += 32)
            Atw[FE * ATW_LD + i] = 0u;
        int sv = (lane < 16) ? g_srcp[e0 + lane] : g_dstp[e0 + lane - 16];
        __syncwarp();

        float c[16][4];
        #pragma unroll
        for (int nt = 0; nt < 16; nt++)
            #pragma unroll
            for (int q = 0; q < 4; q++) c[nt][q] = 0.f;
        #pragma unroll
        for (int kk = 0; kk < 6; kk++) {
            uint32_t a0 = Atw[(8 * kk + tig) * ATW_LD + gid];
            uint32_t a1 = Atw[(8 * kk + tig) * ATW_LD + gid + 8];
            uint32_t a2 = Atw[(8 * kk + tig + 4) * ATW_LD + gid];
            uint32_t a3 = Atw[(8 * kk + tig + 4) * ATW_LD + gid + 8];
            #pragma unroll
            for (int nt = 0; nt < 16; nt++) {
                uint2 b = Bp[(kk * 16 + nt) * 32 + lane];
                mma_tf32(c[nt], a0, a1, a2, a3, b.x, b.y);
            }
        }
        __syncwarp();

        #pragma unroll
        for (int nt = 0; nt < 16; nt++) {
            float2 bi = *reinterpret_cast<const float2*>(&bias_s[nt * 8 + 2 * tig]);
            *reinterpret_cast<float2*>(&EWw[gid * 132 + nt * 8 + 2 * tig]) =
                make_float2(c[nt][0] + bi.x, c[nt][1] + bi.y);
            *reinterpret_cast<float2*>(&EWw[(gid + 8) * 132 + nt * 8 + 2 * tig]) =
                make_float2(c[nt][2] + bi.x, c[nt][3] + bi.y);
        }
        __syncwarp();

        // ---- message phase: bf16 gathers (one uint per lane per operand) ----
        uint32_t fjU[16], sjU[16];
        #pragma unroll
        for (int r = 0; r < 16; r++) {
            int sn = __shfl_sync(0xffffffffu, sv, r);
            fjU[r] = g_HN[(ll)sn * 128 + 64 + lane];
            sjU[r] = g_HN[(ll)sn * 128 + 96 + lane];
        }
        int dprev = -1;
        float fi0 = 0.f, fi1 = 0.f, si0 = 0.f, si1 = 0.f, a0 = 0.f, a1 = 0.f;
        #pragma unroll
        for (int r = 0; r < 16; r++) {
            int d = __shfl_sync(0xffffffffu, sv, 16 + r);
            if (d != dprev) {
                if (dprev >= 0) red2(&acc[(ll)dprev * HD + 2 * lane], a0, a1);
                float2 t0 = bf2f(g_HN[(ll)d * 128 + lane]);
                float2 t1 = bf2f(g_HN[(ll)d * 128 + 32 + lane]);
                fi0 = t0.x; fi1 = t0.y; si0 = t1.x; si1 = t1.y;
                a0 = 0.f; a1 = 0.f;
                dprev = d;
            }
            float2 fj = bf2f(fjU[r]);
            float2 sj = bf2f(sjU[r]);
            float2 ef = *reinterpret_cast<const float2*>(&EWw[r * 132 + 2 * lane]);
            float2 es = *reinterpret_cast<const float2*>(&EWw[r * 132 + 64 + 2 * lane]);
            a0 += sigmoid_f(ef.x + fi0 + fj.x) * softplus_f(es.x + si0 + sj.x);
            a1 += sigmoid_f(ef.y + fi1 + fj.y) * softplus_f(es.y + si1 + sj.y);
        }
        if (dprev >= 0) red2(&acc[(ll)dprev * HD + 2 * lane], a0, a1);
    }
}

// ---------------- BN stats ----------------
__global__ void stats_kernel(int a, const float* __restrict__ buf) {
    __shared__ float s_s[HD], s_q[HD];
    int tid = threadIdx.x;
    if (tid < HD) { s_s[tid] = 0.f; s_q[tid] = 0.f; }
    __syncthreads();
    int col4 = tid & 15;
    float4 ls = make_float4(0.f, 0.f, 0.f, 0.f), lq = ls;
    const float4* acc4 = reinterpret_cast<const float4*>(buf);
    for (int idx4 = blockIdx.x * blockDim.x + tid; idx4 < NN * 16; idx4 += gridDim.x * blockDim.x) {
        float4 v = acc4[idx4];
        ls.x += v.x; lq.x = fmaf(v.x, v.x, lq.x);
        ls.y += v.y; lq.y = fmaf(v.y, v.y, lq.y);
        ls.z += v.z; lq.z = fmaf(v.z, v.z, lq.z);
        ls.w += v.w; lq.w = fmaf(v.w, v.w, lq.w);
    }
    atomicAdd(&s_s[col4 * 4 + 0], ls.x); atomicAdd(&s_q[col4 * 4 + 0], lq.x);
    atomicAdd(&s_s[col4 * 4 + 1], ls.y); atomicAdd(&s_q[col4 * 4 + 1], lq.y);
    atomicAdd(&s_s[col4 * 4 + 2], ls.z); atomicAdd(&s_q[col4 * 4 + 2], lq.z);
    atomicAdd(&s_s[col4 * 4 + 3], ls.w); atomicAdd(&s_q[col4 * 4 + 3], lq.w);
    __syncthreads();
    if (tid < HD) {
        atomicAdd(&g_sum[a * HD + tid], s_s[tid]);
        atomicAdd(&g_sumsq[a * HD + tid], s_q[tid]);
    }
}

// ---------------- final BN + pooling ----------------
__global__ void bn_kernel(const float* __restrict__ gamma, const float* __restrict__ beta,
                          int a, const float* __restrict__ buf,
                          const int* __restrict__ batch) {
    int idx4 = blockIdx.x * blockDim.x + threadIdx.x;
    if (idx4 >= NN * 16) return;
    int col4 = idx4 & 15;
    int node = idx4 >> 4;
    const float invn = 1.0f / (float)NN;
    float4 su = reinterpret_cast<const float4*>(g_sum)[a * 16 + col4];
    float4 sq = reinterpret_cast<const float4*>(g_sumsq)[a * 16 + col4];
    float4 ga = reinterpret_cast<const float4*>(gamma)[col4];
    float4 be = reinterpret_cast<const float4*>(beta)[col4];
    float4 v = reinterpret_cast<const float4*>(buf)[idx4];
    #pragma unroll
    for (int c = 0; c < 4; c++) {
        float mu = (&su.x)[c] * invn;
        float var = fmaxf((&sq.x)[c] * invn - mu * mu, 0.f);
        (&v.x)[c] = ((&v.x)[c] - mu) * rsqrtf(var + BN_EPS) * (&ga.x)[c] + (&be.x)[c];
    }
    int b = batch[node];
    red4(&g_gsum[b * HD + col4 * 4], v);
    if (col4 == 0) atomicAdd(&g_gcnt[b], 1.0f);
}

// ---------------- final MLP ----------------
__global__ void mlp_kernel(const float* __restrict__ W1, const float* __restrict__ b1,
                           const float* __restrict__ W2, const float* __restrict__ b2,
                           const float* __restrict__ Wo, const float* __restrict__ bo,
                           float* __restrict__ out) {
    __shared__ float sW1[HD * HD], sW2[HD * HD], sWo[HD], sb1[HD], sb2[HD];
    int tid = threadIdx.x;
    for (int i = tid; i < HD * HD; i += blockDim.x) { sW1[i] = W1[i]; sW2[i] = W2[i]; }
    if (tid < HD) { sWo[tid] = Wo[tid]; sb1[tid] = b1[tid]; sb2[tid] = b2[tid]; }
    __syncthreads();
    if (tid < NG) {
        float inv = 1.0f / fmaxf(g_gcnt[tid], 1.0f);
        float v[HD], y[HD];
        #pragma unroll
        for (int k = 0; k < HD; k++) v[k] = g_gsum[tid * HD + k] * inv;
        #pragma unroll 1
        for (int j = 0; j < HD; j++) {
            float s = sb1[j];
            #pragma unroll
            for (int k = 0; k < HD; k++) s = fmaf(v[k], sW1[k * HD + j], s);
            y[j] = fmaxf(s, 0.0f) + __logf(1.0f + __expf(-fabsf(s)));
        }
        float o = bo[0];
        #pragma unroll 1
        for (int j = 0; j < HD; j++) {
            float s = sb2[j];
            #pragma unroll
            for (int k = 0; k < HD; k++) s = fmaf(y[k], sW2[k * HD + j], s);
            o = fmaf(fmaxf(s, 0.0f) + __logf(1.0f + __expf(-fabsf(s))), sWo[j], o);
        }
        out[tid] = o;
    }
}

extern "C" void kernel_launch(void* const* d_in, const int* in_sizes, int n_in,
                              void* d_out, int out_size) {
    const float* x         = (const float*)d_in[0];
    const float* edge_attr = (const float*)d_in[1];
    const int*   ei        = (const int*)d_in[2];
    const int*   batch     = (const int*)d_in[3];
    const float* W_emb1    = (const float*)d_in[4];
    const float* b_emb1    = (const float*)d_in[5];
    const float* W_emb2    = (const float*)d_in[6];
    const float* b_emb2    = (const float*)d_in[7];
    const float* Wf        = (const float*)d_in[8];
    const float* bf        = (const float*)d_in[9];
    const float* Ws        = (const float*)d_in[10];
    const float* bs        = (const float*)d_in[11];
    const float* gamma     = (const float*)d_in[12];
    const float* beta      = (const float*)d_in[13];
    const float* W1        = (const float*)d_in[14];
    const float* b1        = (const float*)d_in[15];
    const float* W2        = (const float*)d_in[16];
    const float* b2        = (const float*)d_in[17];
    const float* Wo        = (const float*)d_in[18];
    const float* bo        = (const float*)d_in[19];
    float* out = (float*)d_out;

    float *p_h, *p_acc, *p_Wce, *p_bce, *p_Wnode, *p_sum, *p_sumsq;
    uint32_t* p_HN;
    cudaGetSymbolAddress((void**)&p_h, g_h);
    cudaGetSymbolAddress((void**)&p_acc, g_acc);
    cudaGetSymbolAddress((void**)&p_Wce, g_Wce);
    cudaGetSymbolAddress((void**)&p_bce, g_bce);
    cudaGetSymbolAddress((void**)&p_Wnode, g_Wnode);
    cudaGetSymbolAddress((void**)&p_HN, g_HN);
    cudaGetSymbolAddress((void**)&p_sum, g_sum);
    cudaGetSymbolAddress((void**)&p_sumsq, g_sumsq);

    // fold weights + zero counters/stats
    prep_kernel<<<255, 256>>>(W_emb2, b_emb2, Wf, bf, Ws, bs);

    // sort edges by dst + permute edge_attr
    hist_kernel<<<(NE + 255) / 256, 256>>>(ei);
    scan1_kernel<<<NBLK, 256>>>();
    scan2_kernel<<<1, 256>>>();
    scan3_kernel<<<NBLK, 256>>>();
    scatter_perm_kernel<<<6400, 256>>>(ei, edge_attr);

    cudaFuncSetAttribute(emb_mma_kernel,
                         cudaFuncAttributeMaxDynamicSharedMemorySize, EM_SMEM);
    cudaFuncSetAttribute(node_mma_kernel,
                         cudaFuncAttributeMaxDynamicSharedMemorySize, ND_SMEM);
    cudaFuncSetAttribute(fused_edge_kernel,
                         cudaFuncAttributeMaxDynamicSharedMemorySize, FE_SMEM);

    // h0 = x @ W_emb1 + b_emb1, dual-stored to g_h and g_acc
    emb_mma_kernel<<<148, 512, EM_SMEM>>>(x, W_emb1, b_emb1);

    // ping-pong raw accumulator: L0->g_acc, L1->g_h, L2->g_acc
    float* rawbuf[3] = { p_acc, p_h, p_acc };
    float* srcbuf[3] = { p_h, p_acc, p_h };

    for (int a = 0; a < NCV; a++) {
        const float* bnsum = (a == 0) ? nullptr : p_sum + (a - 1) * HD;
        const float* bnsq  = (a == 0) ? nullptr : p_sumsq + (a - 1) * HD;
        const float* bngam = (a == 0) ? nullptr : gamma + (a - 1) * HD;
        const float* bnbet = (a == 0) ? nullptr : beta + (a - 1) * HD;
        float* wb = (a == 0) ? nullptr : rawbuf[a];
        node_mma_kernel<<<148, 512, ND_SMEM>>>(srcbuf[a],
                                               p_Wnode + (ll)a * HD * 4 * HD,
                                               p_HN, wb, bnsum, bnsq, bngam, bnbet);
        fused_edge_kernel<<<296, 256, FE_SMEM>>>(rawbuf[a],
                                                 p_Wce + a * FE * 2 * HD,
                                                 p_bce + a * 2 * HD);
        stats_kernel<<<296, 256>>>(a, rawbuf[a]);
    }

    // final BN (no relu) + pooling from rawbuf[2]
    bn_kernel<<<(NN * 16 + 255) / 256, 256>>>(gamma + 2 * HD, beta + 2 * HD, 2,
                                              rawbuf[2], batch);

    mlp_kernel<<<1, 128>>>(W1, b1, W2, b2, Wo, bo, out);
}